// round 1
// baseline (speedup 1.0000x reference)
#include <cuda_runtime.h>

#define WSZ   7
#define SHIFT 3
#define RES   56
#define DIMS  192
#define HEADS 6
#define HD    32
#define NTOK  49
#define ROWP  196      // padded row stride (floats) for token-major smem buffers
#define SCP   50       // padded score row stride
#define NTHREADS 384

__global__ __launch_bounds__(NTHREADS, 1)
void swin_attn_kernel(const float* __restrict__ x,
                      const float* __restrict__ table,
                      const float* __restrict__ wq, const float* __restrict__ bq,
                      const float* __restrict__ wk, const float* __restrict__ bk,
                      const float* __restrict__ wv, const float* __restrict__ bv,
                      const float* __restrict__ wo, const float* __restrict__ bo,
                      float* __restrict__ out)
{
    extern __shared__ float smem[];
    float* XW = smem;                          // 49*196, input window; reused as attn output O
    float* Qb = XW + NTOK*ROWP;
    float* Kb = Qb + NTOK*ROWP;
    float* Vb = Kb + NTOK*ROWP;
    float* SC = Vb + NTOK*ROWP;                // 6*49*50 scores
    int*   PIX = (int*)(SC + HEADS*NTOK*SCP);  // 49 pixel base offsets
    int*   CNT = PIX + NTOK;                   // 49 mask region ids

    const int tid = threadIdx.x;
    const int bw  = blockIdx.x;
    const int b   = bw >> 6;                   // batch index
    const int wi  = bw & 63;                   // window index within image
    const int wh  = wi >> 3, ww = wi & 7;
    const int mh  = b  >> 3, mw = b  & 7;      // mask window = BATCH index (reference's repeat quirk)

    if (tid < NTOK) {
        int th = tid / 7, tw = tid % 7;
        int h = wh*7 + th + SHIFT; if (h >= RES) h -= RES;
        int w = ww*7 + tw + SHIFT; if (w >= RES) w -= RES;
        PIX[tid] = ((b*RES + h)*RES + w)*DIMS;
        int mhs = mh*7 + th, mws = mw*7 + tw;
        int rh = (mhs < 49) ? 0 : ((mhs < 53) ? 1 : 2);
        int rw = (mws < 49) ? 0 : ((mws < 53) ? 1 : 2);
        CNT[tid] = rh*3 + rw;
    }
    __syncthreads();

    // ---- Phase 0: gather shifted window into smem (float4 coalesced) ----
    for (int idx = tid; idx < NTOK*(DIMS/4); idx += NTHREADS) {
        int t  = idx / (DIMS/4);
        int c4 = idx - t*(DIMS/4);
        float4 v = *(const float4*)(x + PIX[t] + c4*4);
        *(float4*)(XW + t*ROWP + c4*4) = v;
    }
    __syncthreads();

    // ---- Phase 1: QKV projections. thread owns column c, half of the 49 tokens ----
    const int c    = tid % DIMS;
    const int part = tid / DIMS;       // 0 or 1
    const int t0   = part ? 25 : 0;
    const int tn   = part ? 24 : 25;

    {
        const float* Ws[3] = {wq, wk, wv};
        const float* Bs[3] = {bq, bk, bv};
        float*       Os[3] = {Qb, Kb, Vb};
        #pragma unroll
        for (int m = 0; m < 3; ++m) {
            const float* W = Ws[m];
            float acc[25];
            #pragma unroll
            for (int t = 0; t < 25; ++t) acc[t] = 0.f;
            for (int d0 = 0; d0 < DIMS; d0 += 4) {
                float w0 = W[(d0+0)*DIMS + c];
                float w1 = W[(d0+1)*DIMS + c];
                float w2 = W[(d0+2)*DIMS + c];
                float w3 = W[(d0+3)*DIMS + c];
                #pragma unroll
                for (int t = 0; t < 25; ++t) {
                    if (t < tn) {
                        float4 xv = *(const float4*)(XW + (t0+t)*ROWP + d0);
                        acc[t] = fmaf(xv.x, w0, acc[t]);
                        acc[t] = fmaf(xv.y, w1, acc[t]);
                        acc[t] = fmaf(xv.z, w2, acc[t]);
                        acc[t] = fmaf(xv.w, w3, acc[t]);
                    }
                }
            }
            float bb = Bs[m][c];
            float* O = Os[m];
            #pragma unroll
            for (int t = 0; t < 25; ++t)
                if (t < tn) O[(t0+t)*ROWP + c] = acc[t] + bb;
        }
    }
    __syncthreads();

    // ---- Phase 2: scores = QK^T/sqrt(hd) + rel-pos bias + shift mask ----
    const float scale = 0.17677669529663687f;   // 1/sqrt(32)
    for (int s = tid; s < HEADS*NTOK*NTOK; s += NTHREADS) {
        int h = s / (NTOK*NTOK);
        int r = s - h*(NTOK*NTOK);
        int i = r / NTOK;
        int j = r - i*NTOK;
        const float* qr = Qb + i*ROWP + h*HD;
        const float* kr = Kb + j*ROWP + h*HD;
        float dot = 0.f;
        #pragma unroll
        for (int d = 0; d < HD; d += 4) {
            float4 a  = *(const float4*)(qr + d);
            float4 k4 = *(const float4*)(kr + d);
            dot = fmaf(a.x, k4.x, dot);
            dot = fmaf(a.y, k4.y, dot);
            dot = fmaf(a.z, k4.z, dot);
            dot = fmaf(a.w, k4.w, dot);
        }
        int dh = i/7 - j/7;
        int dw = i%7 - j%7;
        int pidx = (dh + 6)*13 + (dw + 6);
        float bias = __ldg(table + pidx*HEADS + h);
        float mval = (CNT[i] == CNT[j]) ? 0.f : -1000.f;
        SC[(h*NTOK + i)*SCP + j] = fmaf(dot, scale, bias + mval);
    }
    __syncthreads();

    // ---- Phase 3: softmax, one (head,row) per thread ----
    if (tid < HEADS*NTOK) {
        float* p = SC + tid*SCP;
        float mx = -1e30f;
        #pragma unroll 7
        for (int j = 0; j < NTOK; ++j) mx = fmaxf(mx, p[j]);
        float sum = 0.f;
        #pragma unroll 7
        for (int j = 0; j < NTOK; ++j) { float e = __expf(p[j]-mx); p[j] = e; sum += e; }
        float inv = __fdividef(1.f, sum);
        #pragma unroll 7
        for (int j = 0; j < NTOK; ++j) p[j] *= inv;
    }
    __syncthreads();

    // ---- Phase 4: O = P@V, accumulate into XW (xw no longer needed) ----
    for (int s = tid; s < HEADS*NTOK*HD; s += NTHREADS) {
        int h = s / (NTOK*HD);
        int r = s - h*(NTOK*HD);
        int i = r / HD;
        int d = r - i*HD;
        const float* p  = SC + (h*NTOK + i)*SCP;
        const float* vc = Vb + h*HD + d;
        float acc = 0.f;
        #pragma unroll 7
        for (int j = 0; j < NTOK; ++j) acc = fmaf(p[j], vc[j*ROWP], acc);
        XW[i*ROWP + h*HD + d] = acc;
    }
    __syncthreads();

    // ---- Phase 5: output projection + scatter (same pixels as gather) ----
    {
        float acc[25];
        #pragma unroll
        for (int t = 0; t < 25; ++t) acc[t] = 0.f;
        for (int d0 = 0; d0 < DIMS; d0 += 4) {
            float w0 = wo[(d0+0)*DIMS + c];
            float w1 = wo[(d0+1)*DIMS + c];
            float w2 = wo[(d0+2)*DIMS + c];
            float w3 = wo[(d0+3)*DIMS + c];
            #pragma unroll
            for (int t = 0; t < 25; ++t) {
                if (t < tn) {
                    float4 xv = *(const float4*)(XW + (t0+t)*ROWP + d0);
                    acc[t] = fmaf(xv.x, w0, acc[t]);
                    acc[t] = fmaf(xv.y, w1, acc[t]);
                    acc[t] = fmaf(xv.z, w2, acc[t]);
                    acc[t] = fmaf(xv.w, w3, acc[t]);
                }
            }
        }
        float bb = bo[c];
        #pragma unroll
        for (int t = 0; t < 25; ++t)
            if (t < tn) out[PIX[t0+t] + c] = acc[t] + bb;
    }
}

extern "C" void kernel_launch(void* const* d_in, const int* in_sizes, int n_in,
                              void* d_out, int out_size)
{
    const float* x     = (const float*)d_in[0];
    const float* table = (const float*)d_in[1];
    const float* wq    = (const float*)d_in[2];
    const float* bq    = (const float*)d_in[3];
    const float* wk    = (const float*)d_in[4];
    const float* bk    = (const float*)d_in[5];
    const float* wv    = (const float*)d_in[6];
    const float* bv    = (const float*)d_in[7];
    const float* wo    = (const float*)d_in[8];
    const float* bo    = (const float*)d_in[9];
    float* out = (float*)d_out;

    size_t smem_bytes = (size_t)(4*NTOK*ROWP + HEADS*NTOK*SCP)*sizeof(float)
                      + (size_t)(2*NTOK)*sizeof(int);   // ~212.9 KB

    cudaFuncSetAttribute(swin_attn_kernel,
                         cudaFuncAttributeMaxDynamicSharedMemorySize,
                         (int)smem_bytes);

    swin_attn_kernel<<<64*64, NTHREADS, smem_bytes>>>(
        x, table, wq, bq, wk, bk, wv, bv, wo, bo, out);
}

// round 3
// speedup vs baseline: 1.4639x; 1.4639x over previous
#include <cuda_runtime.h>
#include <cuda_bf16.h>
#include <cstdint>

#define RES    56
#define DIMS   192
#define HEADS  6
#define NTOK   49
#define NPIX   200704
#define QKVC   576
#define ASTRIDE 200          // A smem row stride in bf16 elems (400B -> ldmatrix conflict-free)

// static device scratch (no runtime allocation allowed)
__device__ float g_qkv[(size_t)NPIX * QKVC];   // 462 MB
__device__ float g_att[(size_t)NPIX * DIMS];   // 154 MB
__device__ uint4 g_wfrag[96 * 12 * 32];        // B fragments: 96 ntiles x 12 ksteps x 32 lanes
__device__ float g_bias[768];                  // bq|bk|bv (576) then bo (192)

__device__ __forceinline__ uint32_t smem_u32(const void* p){
    uint32_t a;
    asm("{ .reg .u64 t; cvta.to.shared.u64 t, %1; cvt.u32.u64 %0, t; }" : "=r"(a) : "l"(p));
    return a;
}
__device__ __forceinline__ uint32_t pack2(__nv_bfloat16 a, __nv_bfloat16 b){
    return (uint32_t)__bfloat16_as_ushort(a) | ((uint32_t)__bfloat16_as_ushort(b) << 16);
}
__device__ __forceinline__ void ldmx4(uint32_t* r, uint32_t addr){
    asm volatile("ldmatrix.sync.aligned.m8n8.x4.shared.b16 {%0,%1,%2,%3}, [%4];"
        : "=r"(r[0]), "=r"(r[1]), "=r"(r[2]), "=r"(r[3]) : "r"(addr));
}
__device__ __forceinline__ void mma16816(float* c, const uint32_t* a, uint32_t b0, uint32_t b1){
    asm volatile("mma.sync.aligned.m16n8k16.row.col.f32.bf16.bf16.f32 "
        "{%0,%1,%2,%3}, {%4,%5,%6,%7}, {%8,%9}, {%0,%1,%2,%3};"
        : "+f"(c[0]), "+f"(c[1]), "+f"(c[2]), "+f"(c[3])
        : "r"(a[0]), "r"(a[1]), "r"(a[2]), "r"(a[3]), "r"(b0), "r"(b1));
}

// =====================================================================
// One-time weight prep: bf16 hi/lo B-fragments in mma lane order + bias
// B frag (m16n8k16): lane l holds B[k0+{0,1}][n], B[k0+8+{0,1}][n],
// k0 = ks*16 + (l%4)*2, n = ntile*8 + l/4.
// ntiles 0..71 -> [wq|wk|wv] cols 0..575 ; ntiles 72..95 -> wo cols 0..191
// =====================================================================
__global__ void wprep_kernel(const float* __restrict__ wq, const float* __restrict__ wk,
                             const float* __restrict__ wv, const float* __restrict__ wo,
                             const float* __restrict__ bq, const float* __restrict__ bk,
                             const float* __restrict__ bv, const float* __restrict__ bo)
{
    int t = blockIdx.x * 256 + threadIdx.x;
    if (t < 768){
        float b;
        if      (t < 192) b = bq[t];
        else if (t < 384) b = bk[t - 192];
        else if (t < 576) b = bv[t - 384];
        else              b = bo[t - 576];
        g_bias[t] = b;
    }
    if (t >= 96*12*32) return;
    int ntile = t / 384;
    int rem   = t - ntile*384;
    int ks    = rem >> 5;
    int lane  = rem & 31;
    int nl    = lane >> 2;
    int k0    = ks*16 + (lane & 3)*2;

    const float* W; int col;
    if (ntile < 72){
        int ng = ntile*8 + nl;
        int mat = ng / 192; col = ng - mat*192;
        W = (mat == 0) ? wq : ((mat == 1) ? wk : wv);
    } else {
        col = (ntile - 72)*8 + nl;
        W = wo;
    }
    float e0 = W[(k0+0)*192 + col], e1 = W[(k0+1)*192 + col];
    float e2 = W[(k0+8)*192 + col], e3 = W[(k0+9)*192 + col];
    __nv_bfloat16 h0 = __float2bfloat16(e0), h1 = __float2bfloat16(e1),
                  h2 = __float2bfloat16(e2), h3 = __float2bfloat16(e3);
    __nv_bfloat16 l0 = __float2bfloat16(e0 - __bfloat162float(h0)),
                  l1 = __float2bfloat16(e1 - __bfloat162float(h1)),
                  l2 = __float2bfloat16(e2 - __bfloat162float(h2)),
                  l3 = __float2bfloat16(e3 - __bfloat162float(h3));
    uint4 v;
    v.x = pack2(h0, h1);
    v.y = pack2(h2, h3);
    v.z = pack2(l0, l1);
    v.w = pack2(l2, l3);
    g_wfrag[t] = v;
}

// =====================================================================
// GEMM: Out[128-tile rows][col=nt*8..] = A[128x192] @ Wfrag(ntStart+nt) + bias
// 3-term bf16 (AhBh + AlBh + AhBl), fp32 accum. 8 warps x 16 rows.
// =====================================================================
#define GEMM_SMEM (2 * 128 * ASTRIDE * 2)

__global__ __launch_bounds__(256, 2)
void mma_gemm(const float* __restrict__ A, float* __restrict__ Out,
              int outStride, int ntStart, int ntCount, int biasOff)
{
    extern __shared__ char smc[];
    __nv_bfloat16* sH = (__nv_bfloat16*)smc;
    __nv_bfloat16* sL = sH + 128 * ASTRIDE;

    const int tid = threadIdx.x, wid = tid >> 5, lane = tid & 31;
    const float* Ab = A + (size_t)blockIdx.x * 128 * 192;

    // ---- convert A tile to bf16 hi/lo in smem ----
    for (int f = tid; f < 6144; f += 256){
        int r  = f / 48;
        int kk = (f - r*48) * 4;
        float4 v = *(const float4*)(Ab + r*192 + kk);
        __nv_bfloat16 h0 = __float2bfloat16(v.x), h1 = __float2bfloat16(v.y),
                      h2 = __float2bfloat16(v.z), h3 = __float2bfloat16(v.w);
        __nv_bfloat16 l0 = __float2bfloat16(v.x - __bfloat162float(h0)),
                      l1 = __float2bfloat16(v.y - __bfloat162float(h1)),
                      l2 = __float2bfloat16(v.z - __bfloat162float(h2)),
                      l3 = __float2bfloat16(v.w - __bfloat162float(h3));
        uint2 hv, lv;
        hv.x = pack2(h0, h1); hv.y = pack2(h2, h3);
        lv.x = pack2(l0, l1); lv.y = pack2(l2, l3);
        *(uint2*)(sH + r*ASTRIDE + kk) = hv;
        *(uint2*)(sL + r*ASTRIDE + kk) = lv;
    }
    __syncthreads();

    // ---- load A fragments (persistent in registers) ----
    uint32_t ah[12][4], al[12][4];
    {
        int row  = wid*16 + (lane & 15);
        int coff = (lane >> 4) * 8;
        #pragma unroll
        for (int ks = 0; ks < 12; ++ks){
            uint32_t aH = smem_u32(sH + row*ASTRIDE + ks*16 + coff);
            uint32_t aL = smem_u32(sL + row*ASTRIDE + ks*16 + coff);
            ldmx4(ah[ks], aH);
            ldmx4(al[ks], aL);
        }
    }

    const int rowg = blockIdx.x*128 + wid*16 + (lane >> 2);
    const int cloc = (lane & 3) * 2;

    for (int nt = 0; nt < ntCount; ++nt){
        const uint4* bp = g_wfrag + (size_t)(ntStart + nt)*384 + lane;
        float c0[4] = {0,0,0,0}, c1[4] = {0,0,0,0}, c2[4] = {0,0,0,0};
        #pragma unroll
        for (int ks = 0; ks < 12; ++ks){
            uint4 bv = bp[ks*32];
            mma16816(c0, ah[ks], bv.x, bv.y);   // Ah * Bh
            mma16816(c1, al[ks], bv.x, bv.y);   // Al * Bh
            mma16816(c2, ah[ks], bv.z, bv.w);   // Ah * Bl
        }
        int cb = nt*8 + cloc;
        float b0 = g_bias[biasOff + cb], b1 = g_bias[biasOff + cb + 1];
        float2 o0, o1;
        o0.x = c0[0] + c1[0] + c2[0] + b0;
        o0.y = c0[1] + c1[1] + c2[1] + b1;
        o1.x = c0[2] + c1[2] + c2[2] + b0;
        o1.y = c0[3] + c1[3] + c2[3] + b1;
        *(float2*)(Out + (size_t)rowg     * outStride + cb) = o0;
        *(float2*)(Out + (size_t)(rowg+8) * outStride + cb) = o1;
    }
}

// =====================================================================
// Attention kernel: one CTA per (batch, window). fp32.
// =====================================================================
#define QROW 580
#define ATTN_SMEM ((NTOK*QROW + HEADS*NTOK*50)*4 + 2*NTOK*4)

__global__ __launch_bounds__(384, 1)
void attn_kernel(const float* __restrict__ table,
                 const float* __restrict__ qkv,
                 float* __restrict__ att)
{
    extern __shared__ float sf[];
    float* QKV = sf;                          // 49 x 580
    float* SC  = QKV + NTOK*QROW;             // 6*49*50
    int*   PIX = (int*)(SC + HEADS*NTOK*50);
    int*   CNT = PIX + NTOK;

    const int tid = threadIdx.x;
    const int bw = blockIdx.x;
    const int b  = bw >> 6, wi = bw & 63;
    const int wh = wi >> 3, ww = wi & 7;
    const int mh = b >> 3,  mw = b & 7;       // mask window = BATCH index (reference quirk)

    if (tid < NTOK){
        int th = tid / 7, tw = tid - th*7;
        int hh = wh*7 + th + 3; if (hh >= RES) hh -= RES;
        int wc = ww*7 + tw + 3; if (wc >= RES) wc -= RES;
        PIX[tid] = (b*RES + hh)*RES + wc;
        int mhs = mh*7 + th, mws = mw*7 + tw;
        int rh = (mhs < 49) ? 0 : ((mhs < 53) ? 1 : 2);
        int rw = (mws < 49) ? 0 : ((mws < 53) ? 1 : 2);
        CNT[tid] = rh*3 + rw;
    }
    __syncthreads();

    for (int f = tid; f < NTOK*144; f += 384){
        int t  = f / 144;
        int c4 = f - t*144;
        float4 v = *(const float4*)(qkv + (size_t)PIX[t]*QKVC + c4*4);
        *(float4*)(QKV + t*QROW + c4*4) = v;
    }
    __syncthreads();

    if (tid < HEADS*NTOK){
        const int h = tid / NTOK;
        const int i = tid - h*NTOK;
        const int ih = i / 7, iw = i - ih*7;
        const int ci = CNT[i];
        const float scale = 0.17677669529663687f;

        float4 q[8];
        const float4* qp = (const float4*)(QKV + i*QROW + h*32);
        #pragma unroll
        for (int d = 0; d < 8; ++d) q[d] = qp[d];

        float* srow = SC + (h*NTOK + i)*50;
        int jh = 0, jw = 0;
        for (int j = 0; j < NTOK; ++j){
            const float4* kr = (const float4*)(QKV + j*QROW + 192 + h*32);
            float a0 = 0.f, a1 = 0.f;
            #pragma unroll
            for (int d = 0; d < 8; d += 2){
                float4 k0 = kr[d], k1 = kr[d+1];
                a0 = fmaf(q[d].x,   k0.x, a0); a0 = fmaf(q[d].y,   k0.y, a0);
                a0 = fmaf(q[d].z,   k0.z, a0); a0 = fmaf(q[d].w,   k0.w, a0);
                a1 = fmaf(q[d+1].x, k1.x, a1); a1 = fmaf(q[d+1].y, k1.y, a1);
                a1 = fmaf(q[d+1].z, k1.z, a1); a1 = fmaf(q[d+1].w, k1.w, a1);
            }
            float bias = __ldg(table + ((ih - jh + 6)*13 + (iw - jw + 6))*HEADS + h);
            float mv = (ci == CNT[j]) ? 0.f : -1000.f;
            srow[j] = fmaf(a0 + a1, scale, bias + mv);
            if (++jw == 7){ jw = 0; ++jh; }
        }

        float mx = -1e30f;
        #pragma unroll 7
        for (int j = 0; j < NTOK; ++j) mx = fmaxf(mx, srow[j]);
        float sum = 0.f;
        #pragma unroll 7
        for (int j = 0; j < NTOK; ++j){ float e = __expf(srow[j] - mx); srow[j] = e; sum += e; }
        float inv = __fdividef(1.f, sum);

        float acc[32];
        #pragma unroll
        for (int d = 0; d < 32; ++d) acc[d] = 0.f;
        for (int j = 0; j < NTOK; ++j){
            float p = srow[j];
            const float4* vr = (const float4*)(QKV + j*QROW + 384 + h*32);
            #pragma unroll
            for (int d = 0; d < 8; ++d){
                float4 vv = vr[d];
                acc[d*4+0] = fmaf(p, vv.x, acc[d*4+0]);
                acc[d*4+1] = fmaf(p, vv.y, acc[d*4+1]);
                acc[d*4+2] = fmaf(p, vv.z, acc[d*4+2]);
                acc[d*4+3] = fmaf(p, vv.w, acc[d*4+3]);
            }
        }
        float* ob = att + (size_t)PIX[i]*DIMS + h*32;
        #pragma unroll
        for (int d = 0; d < 8; ++d){
            float4 o;
            o.x = acc[d*4+0]*inv; o.y = acc[d*4+1]*inv;
            o.z = acc[d*4+2]*inv; o.w = acc[d*4+3]*inv;
            *(float4*)(ob + d*4) = o;
        }
    }
}

// =====================================================================
extern "C" void kernel_launch(void* const* d_in, const int* in_sizes, int n_in,
                              void* d_out, int out_size)
{
    const float* x     = (const float*)d_in[0];
    const float* table = (const float*)d_in[1];
    const float* wq    = (const float*)d_in[2];
    const float* bq    = (const float*)d_in[3];
    const float* wk    = (const float*)d_in[4];
    const float* bk    = (const float*)d_in[5];
    const float* wv    = (const float*)d_in[6];
    const float* bv    = (const float*)d_in[7];
    const float* wo    = (const float*)d_in[8];
    const float* bo    = (const float*)d_in[9];
    float* out = (float*)d_out;

    void* qkvp = nullptr; void* attp = nullptr;
    cudaGetSymbolAddress(&qkvp, g_qkv);
    cudaGetSymbolAddress(&attp, g_att);

    cudaFuncSetAttribute(mma_gemm,    cudaFuncAttributeMaxDynamicSharedMemorySize, GEMM_SMEM);
    cudaFuncSetAttribute(attn_kernel, cudaFuncAttributeMaxDynamicSharedMemorySize, ATTN_SMEM);

    // 0) one-time weight fragment prep (cheap; rerun every call for determinism)
    wprep_kernel<<<144, 256>>>(wq, wk, wv, wo, bq, bk, bv, bo);
    // 1) QKV projection
    mma_gemm<<<NPIX/128, 256, GEMM_SMEM>>>(x, (float*)qkvp, QKVC, 0, 72, 0);
    // 2) windowed attention
    attn_kernel<<<64*64, 384, ATTN_SMEM>>>(table, (const float*)qkvp, (float*)attp);
    // 3) output projection
    mma_gemm<<<NPIX/128, 256, GEMM_SMEM>>>((const float*)attp, out, DIMS, 72, 24, 576);
}

// round 4
// speedup vs baseline: 1.7226x; 1.1767x over previous
#include <cuda_runtime.h>
#include <cuda_bf16.h>
#include <cstdint>

#define RES    56
#define DIMS   192
#define HEADS  6
#define NTOK   49
#define NPIX   200704
#define QKVC   576
#define ASTRIDE 200          // A smem row stride in bf16 elems (400B -> ldmatrix conflict-free)

// static device scratch (no runtime allocation allowed)
__device__ float g_qkv[(size_t)NPIX * QKVC];   // 462 MB
__device__ float g_att[(size_t)NPIX * DIMS];   // 154 MB
__device__ uint4 g_wfrag[96 * 12 * 32];        // B fragments: 96 ntiles x 12 ksteps x 32 lanes
__device__ float g_bias[768];                  // bq|bk|bv (576) then bo (192)

__device__ __forceinline__ uint32_t smem_u32(const void* p){
    uint32_t a;
    asm("{ .reg .u64 t; cvta.to.shared.u64 t, %1; cvt.u32.u64 %0, t; }" : "=r"(a) : "l"(p));
    return a;
}
__device__ __forceinline__ uint32_t pack2(__nv_bfloat16 a, __nv_bfloat16 b){
    return (uint32_t)__bfloat16_as_ushort(a) | ((uint32_t)__bfloat16_as_ushort(b) << 16);
}
__device__ __forceinline__ void ldmx4(uint32_t* r, uint32_t addr){
    asm volatile("ldmatrix.sync.aligned.m8n8.x4.shared.b16 {%0,%1,%2,%3}, [%4];"
        : "=r"(r[0]), "=r"(r[1]), "=r"(r[2]), "=r"(r[3]) : "r"(addr));
}
__device__ __forceinline__ void mma16816(float* c, const uint32_t* a, uint32_t b0, uint32_t b1){
    asm volatile("mma.sync.aligned.m16n8k16.row.col.f32.bf16.bf16.f32 "
        "{%0,%1,%2,%3}, {%4,%5,%6,%7}, {%8,%9}, {%0,%1,%2,%3};"
        : "+f"(c[0]), "+f"(c[1]), "+f"(c[2]), "+f"(c[3])
        : "r"(a[0]), "r"(a[1]), "r"(a[2]), "r"(a[3]), "r"(b0), "r"(b1));
}

// =====================================================================
// One-time weight prep (unchanged from R3)
// =====================================================================
__global__ void wprep_kernel(const float* __restrict__ wq, const float* __restrict__ wk,
                             const float* __restrict__ wv, const float* __restrict__ wo,
                             const float* __restrict__ bq, const float* __restrict__ bk,
                             const float* __restrict__ bv, const float* __restrict__ bo)
{
    int t = blockIdx.x * 256 + threadIdx.x;
    if (t < 768){
        float b;
        if      (t < 192) b = bq[t];
        else if (t < 384) b = bk[t - 192];
        else if (t < 576) b = bv[t - 384];
        else              b = bo[t - 576];
        g_bias[t] = b;
    }
    if (t >= 96*12*32) return;
    int ntile = t / 384;
    int rem   = t - ntile*384;
    int ks    = rem >> 5;
    int lane  = rem & 31;
    int nl    = lane >> 2;
    int k0    = ks*16 + (lane & 3)*2;

    const float* W; int col;
    if (ntile < 72){
        int ng = ntile*8 + nl;
        int mat = ng / 192; col = ng - mat*192;
        W = (mat == 0) ? wq : ((mat == 1) ? wk : wv);
    } else {
        col = (ntile - 72)*8 + nl;
        W = wo;
    }
    float e0 = W[(k0+0)*192 + col], e1 = W[(k0+1)*192 + col];
    float e2 = W[(k0+8)*192 + col], e3 = W[(k0+9)*192 + col];
    __nv_bfloat16 h0 = __float2bfloat16(e0), h1 = __float2bfloat16(e1),
                  h2 = __float2bfloat16(e2), h3 = __float2bfloat16(e3);
    __nv_bfloat16 l0 = __float2bfloat16(e0 - __bfloat162float(h0)),
                  l1 = __float2bfloat16(e1 - __bfloat162float(h1)),
                  l2 = __float2bfloat16(e2 - __bfloat162float(h2)),
                  l3 = __float2bfloat16(e3 - __bfloat162float(h3));
    uint4 v;
    v.x = pack2(h0, h1);
    v.y = pack2(h2, h3);
    v.z = pack2(l0, l1);
    v.w = pack2(l2, l3);
    g_wfrag[t] = v;
}

// =====================================================================
// GEMM (unchanged from R3): 3-term bf16 MMA, fp32 accum
// =====================================================================
#define GEMM_SMEM (2 * 128 * ASTRIDE * 2)

__global__ __launch_bounds__(256, 2)
void mma_gemm(const float* __restrict__ A, float* __restrict__ Out,
              int outStride, int ntStart, int ntCount, int biasOff)
{
    extern __shared__ char smc[];
    __nv_bfloat16* sH = (__nv_bfloat16*)smc;
    __nv_bfloat16* sL = sH + 128 * ASTRIDE;

    const int tid = threadIdx.x, wid = tid >> 5, lane = tid & 31;
    const float* Ab = A + (size_t)blockIdx.x * 128 * 192;

    for (int f = tid; f < 6144; f += 256){
        int r  = f / 48;
        int kk = (f - r*48) * 4;
        float4 v = *(const float4*)(Ab + r*192 + kk);
        __nv_bfloat16 h0 = __float2bfloat16(v.x), h1 = __float2bfloat16(v.y),
                      h2 = __float2bfloat16(v.z), h3 = __float2bfloat16(v.w);
        __nv_bfloat16 l0 = __float2bfloat16(v.x - __bfloat162float(h0)),
                      l1 = __float2bfloat16(v.y - __bfloat162float(h1)),
                      l2 = __float2bfloat16(v.z - __bfloat162float(h2)),
                      l3 = __float2bfloat16(v.w - __bfloat162float(h3));
        uint2 hv, lv;
        hv.x = pack2(h0, h1); hv.y = pack2(h2, h3);
        lv.x = pack2(l0, l1); lv.y = pack2(l2, l3);
        *(uint2*)(sH + r*ASTRIDE + kk) = hv;
        *(uint2*)(sL + r*ASTRIDE + kk) = lv;
    }
    __syncthreads();

    uint32_t ah[12][4], al[12][4];
    {
        int row  = wid*16 + (lane & 15);
        int coff = (lane >> 4) * 8;
        #pragma unroll
        for (int ks = 0; ks < 12; ++ks){
            uint32_t aH = smem_u32(sH + row*ASTRIDE + ks*16 + coff);
            uint32_t aL = smem_u32(sL + row*ASTRIDE + ks*16 + coff);
            ldmx4(ah[ks], aH);
            ldmx4(al[ks], aL);
        }
    }

    const int rowg = blockIdx.x*128 + wid*16 + (lane >> 2);
    const int cloc = (lane & 3) * 2;

    for (int nt = 0; nt < ntCount; ++nt){
        const uint4* bp = g_wfrag + (size_t)(ntStart + nt)*384 + lane;
        float c0[4] = {0,0,0,0}, c1[4] = {0,0,0,0}, c2[4] = {0,0,0,0};
        #pragma unroll
        for (int ks = 0; ks < 12; ++ks){
            uint4 bv = bp[ks*32];
            mma16816(c0, ah[ks], bv.x, bv.y);
            mma16816(c1, al[ks], bv.x, bv.y);
            mma16816(c2, ah[ks], bv.z, bv.w);
        }
        int cb = nt*8 + cloc;
        float b0 = g_bias[biasOff + cb], b1 = g_bias[biasOff + cb + 1];
        float2 o0, o1;
        o0.x = c0[0] + c1[0] + c2[0] + b0;
        o0.y = c0[1] + c1[1] + c2[1] + b1;
        o1.x = c0[2] + c1[2] + c2[2] + b0;
        o1.y = c0[3] + c1[3] + c2[3] + b1;
        *(float2*)(Out + (size_t)rowg     * outStride + cb) = o0;
        *(float2*)(Out + (size_t)(rowg+8) * outStride + cb) = o1;
    }
}

// =====================================================================
// Attention: one CTA per (window, head). 64 threads, ~23.6 KB smem.
// Thread i (<49) owns query row i: Q in regs, K/V smem broadcasts.
// =====================================================================
#define SCP 51

__global__ __launch_bounds__(64, 9)
void attn_kernel(const float* __restrict__ table,
                 const float* __restrict__ qkv,
                 float* __restrict__ att)
{
    __shared__ float sK[NTOK*32];
    __shared__ float sV[NTOK*32];
    __shared__ float sSC[NTOK*SCP];
    __shared__ float sB[169];
    __shared__ int   PIX[NTOK];
    __shared__ int   CNT[NTOK];

    const int tid = threadIdx.x;
    const int win = blockIdx.x;
    const int h   = blockIdx.y;
    const int b   = win >> 6, wi = win & 63;
    const int wh  = wi >> 3,  ww = wi & 7;
    const int mh  = b >> 3,   mw = b & 7;   // mask window = BATCH index (reference quirk)

    if (tid < NTOK){
        int th = tid / 7, tw = tid - th*7;
        int hh = wh*7 + th + 3; if (hh >= RES) hh -= RES;
        int wc = ww*7 + tw + 3; if (wc >= RES) wc -= RES;
        PIX[tid] = (b*RES + hh)*RES + wc;
        int mhs = mh*7 + th, mws = mw*7 + tw;
        int rh = (mhs < 49) ? 0 : ((mhs < 53) ? 1 : 2);
        int rw = (mws < 49) ? 0 : ((mws < 53) ? 1 : 2);
        CNT[tid] = rh*3 + rw;
    }
    // bias table slice for this head
    for (int t = tid; t < 169; t += 64) sB[t] = __ldg(table + t*HEADS + h);
    __syncthreads();

    // gather K, V for this head (49 x 32 each)
    for (int f = tid; f < NTOK*8; f += 64){
        int t  = f >> 3;
        int c4 = (f & 7) * 4;
        const float* base = qkv + (size_t)PIX[t]*QKVC + h*32;
        *(float4*)(sK + t*32 + c4) = *(const float4*)(base + 192 + c4);
        *(float4*)(sV + t*32 + c4) = *(const float4*)(base + 384 + c4);
    }
    __syncthreads();

    if (tid < NTOK){
        const int i  = tid;
        const int ih = i / 7, iw = i - ih*7;
        const int ci = CNT[i];
        const float scale = 0.17677669529663687f;

        // Q row -> registers (direct from global)
        float4 q[8];
        const float4* qp = (const float4*)(qkv + (size_t)PIX[i]*QKVC + h*32);
        #pragma unroll
        for (int d = 0; d < 8; ++d) q[d] = qp[d];

        // ---- scores + bias + mask ----
        float* srow = sSC + i*SCP;
        int jh = 0, jw = 0;
        for (int j = 0; j < NTOK; ++j){
            const float4* kr = (const float4*)(sK + j*32);
            float a0 = 0.f, a1 = 0.f;
            #pragma unroll
            for (int d = 0; d < 8; d += 2){
                float4 k0 = kr[d], k1 = kr[d+1];
                a0 = fmaf(q[d].x,   k0.x, a0); a0 = fmaf(q[d].y,   k0.y, a0);
                a0 = fmaf(q[d].z,   k0.z, a0); a0 = fmaf(q[d].w,   k0.w, a0);
                a1 = fmaf(q[d+1].x, k1.x, a1); a1 = fmaf(q[d+1].y, k1.y, a1);
                a1 = fmaf(q[d+1].z, k1.z, a1); a1 = fmaf(q[d+1].w, k1.w, a1);
            }
            float bias = sB[(ih - jh + 6)*13 + (iw - jw + 6)];
            float mv = (ci == CNT[j]) ? 0.f : -1000.f;
            srow[j] = fmaf(a0 + a1, scale, bias + mv);
            if (++jw == 7){ jw = 0; ++jh; }
        }

        // ---- softmax ----
        float mx = -1e30f;
        #pragma unroll 7
        for (int j = 0; j < NTOK; ++j) mx = fmaxf(mx, srow[j]);
        float sum = 0.f;
        #pragma unroll 7
        for (int j = 0; j < NTOK; ++j){ float e = __expf(srow[j] - mx); srow[j] = e; sum += e; }
        float inv = __fdividef(1.f, sum);

        // ---- O = P @ V ----
        float acc[32];
        #pragma unroll
        for (int d = 0; d < 32; ++d) acc[d] = 0.f;
        for (int j = 0; j < NTOK; ++j){
            float p = srow[j];
            const float4* vr = (const float4*)(sV + j*32);
            #pragma unroll
            for (int d = 0; d < 8; ++d){
                float4 vv = vr[d];
                acc[d*4+0] = fmaf(p, vv.x, acc[d*4+0]);
                acc[d*4+1] = fmaf(p, vv.y, acc[d*4+1]);
                acc[d*4+2] = fmaf(p, vv.z, acc[d*4+2]);
                acc[d*4+3] = fmaf(p, vv.w, acc[d*4+3]);
            }
        }
        float* ob = att + (size_t)PIX[i]*DIMS + h*32;
        #pragma unroll
        for (int d = 0; d < 8; ++d){
            float4 o;
            o.x = acc[d*4+0]*inv; o.y = acc[d*4+1]*inv;
            o.z = acc[d*4+2]*inv; o.w = acc[d*4+3]*inv;
            *(float4*)(ob + d*4) = o;
        }
    }
}

// =====================================================================
extern "C" void kernel_launch(void* const* d_in, const int* in_sizes, int n_in,
                              void* d_out, int out_size)
{
    const float* x     = (const float*)d_in[0];
    const float* table = (const float*)d_in[1];
    const float* wq    = (const float*)d_in[2];
    const float* bq    = (const float*)d_in[3];
    const float* wk    = (const float*)d_in[4];
    const float* bk    = (const float*)d_in[5];
    const float* wv    = (const float*)d_in[6];
    const float* bv    = (const float*)d_in[7];
    const float* wo    = (const float*)d_in[8];
    const float* bo    = (const float*)d_in[9];
    float* out = (float*)d_out;

    void* qkvp = nullptr; void* attp = nullptr;
    cudaGetSymbolAddress(&qkvp, g_qkv);
    cudaGetSymbolAddress(&attp, g_att);

    cudaFuncSetAttribute(mma_gemm, cudaFuncAttributeMaxDynamicSharedMemorySize, GEMM_SMEM);

    // 0) weight fragment prep
    wprep_kernel<<<144, 256>>>(wq, wk, wv, wo, bq, bk, bv, bo);
    // 1) QKV projection
    mma_gemm<<<NPIX/128, 256, GEMM_SMEM>>>(x, (float*)qkvp, QKVC, 0, 72, 0);
    // 2) windowed attention, one CTA per (window, head)
    dim3 ag(4096, 6);
    attn_kernel<<<ag, 64>>>(table, (const float*)qkvp, (float*)attp);
    // 3) output projection
    mma_gemm<<<NPIX/128, 256, GEMM_SMEM>>>((const float*)attp, out, DIMS, 72, 24, 576);
}